// round 10
// baseline (speedup 1.0000x reference)
#include <cuda_runtime.h>

#define NQ 13
#define FULL 0xffffffffu

// Transfer-matrix contraction (bond dim 4, Hermitian-reduced).
// One warp per batch element, 4 warps per CTA (128 CTAs -> 128 SMs active,
// 1 warp per SMSP: minimum per-SMSP issue load for 512 total warps).
//   - lanes 0..12:  layer-1 params (phi) for wire l          (3 sincosf)
//   - lanes 16..28: layer-2 params (m, mu) for wire l-16     (2 sincosf)
//   - all lanes redundantly run the 13-step chain, pulling lane q's params
//     via __shfl_sync; kappa is derived in-lane from the shuffled phi
//     (2 FFMA) instead of a 13th shuffle stream.
//   - ev[q] kept by lane q -> one coalesced 13-lane store.
// Math (verified R5-R9):
//   layer-2 M = U2+ Z U2, RZ cancels: m = cos t1 cos t2,
//     mu = -sin t2 - i sin t1 cos t2  (FULL angles t = x*w)
//   layer-1 phi = first column of RZ*RY*RX (half angles)
//   CNOT chain = Gray perm -> nearest-neighbor transfer chain; identity tail
//   telescopes to boundary factor kappa_{q+1} = 2 Re(conj(phi0) phi1).
__global__ __launch_bounds__(128, 1)
void qsim_tn(const float* __restrict__ x,
             const float* __restrict__ wts,
             float* __restrict__ out,
             int n)
{
    const int e = blockIdx.x * 4 + (threadIdx.x >> 5);
    const int l = threadIdx.x & 31;
    if (e >= n) return;

    // ---- per-lane gate parameters ----
    float p0x = 0.f, p0y = 0.f, p1x = 0.f, p1y = 0.f;
    float m = 0.f, mux = 0.f, muy = 0.f;

    if (l < NQ) {
        // layer-1 wire l
        const float xv = __ldg(&x[e * NQ + l]);
        const float w0 = __ldg(&wts[l * 3 + 0]);
        const float w1 = __ldg(&wts[l * 3 + 1]);
        const float w2 = __ldg(&wts[l * 3 + 2]);
        float s1, c1, s2, c2, sp, cp;
        __sincosf(0.5f * xv * w0, &s1, &c1);   // RX half
        __sincosf(0.5f * xv * w1, &s2, &c2);   // RY half
        __sincosf(0.5f * w2,      &sp, &cp);   // RZ half
        const float A = c2 * c1, B = s2 * s1, C = s2 * c1, D = c2 * s1;
        p0x = fmaf(cp, A,  sp * B);
        p0y = fmaf(cp, B, -sp * A);
        p1x = fmaf(cp, C,  sp * D);
        p1y = fmaf(sp, C, -cp * D);
    } else if (l >= 16 && l < 16 + NQ) {
        // layer-2 wire (l-16); RZ cancels in M = U+ Z U
        const int q = l - 16;
        const float xv = __ldg(&x[e * NQ + q]);
        const float w0 = __ldg(&wts[(NQ + q) * 3 + 0]);
        const float w1 = __ldg(&wts[(NQ + q) * 3 + 1]);
        float sa, ca, sb, cb;
        __sincosf(xv * w0, &sa, &ca);          // full angles
        __sincosf(xv * w1, &sb, &cb);
        m   = ca * cb;
        mux = -sb;
        muy = -sa * cb;
    }

    // ---- sequential chain, all lanes; params broadcast per step ----
    float v00 = 0.f, v11 = 0.f, v01x = 0.f, v01y = 0.f;
    float my_ev = 0.f;

    #pragma unroll
    for (int q = 0; q < NQ; q++) {
        const float g0x = __shfl_sync(FULL, p0x, q);
        const float g0y = __shfl_sync(FULL, p0y, q);
        const float g1x = __shfl_sync(FULL, p1x, q);
        const float g1y = __shfl_sync(FULL, p1y, q);
        const float gm  = __shfl_sync(FULL, m,   16 + q);
        const float gux = __shfl_sync(FULL, mux, 16 + q);
        const float guy = __shfl_sync(FULL, muy, 16 + q);

        if (q > 0) {
            // kappa of wire q derived in-lane: 2 Re(conj(phi0) phi1)
            const float gk = 2.f * fmaf(g0x, g1x, g0y * g1y);
            const float ev = v00 + v11 + gk * (2.f * v01x);
            if (l == q - 1) my_ev = ev;
        }

        if (q == 0) {
            v00  =  gm * fmaf(g0x, g0x, g0y * g0y);
            v11  = -gm * fmaf(g1x, g1x, g1y * g1y);
            const float tx = fmaf(g0x, g1x,  g0y * g1y);   // conj(p0)*p1
            const float ty = fmaf(g0x, g1y, -g0y * g1x);
            v01x = fmaf(gux, tx, -guy * ty);
            v01y = fmaf(gux, ty,  guy * tx);
        } else {
            // h(c,a') = sum_{c'} phi(a'^c') v(c,c')
            const float h00x = fmaf(g0x, v00, fmaf(g1x, v01x, -g1y * v01y));
            const float h00y = fmaf(g0y, v00, fmaf(g1x, v01y,  g1y * v01x));
            const float h01x = fmaf(g1x, v00, fmaf(g0x, v01x, -g0y * v01y));
            const float h01y = fmaf(g1y, v00, fmaf(g0x, v01y,  g0y * v01x));
            const float h10x = fmaf(g1x, v11, fmaf(g0x, v01x,  g0y * v01y));
            const float h10y = fmaf(g1y, v11, fmaf(g0y, v01x, -g0x * v01y));
            const float h11x = fmaf(g0x, v11, fmaf(g1x, v01x,  g1y * v01y));
            const float h11y = fmaf(g0y, v11, fmaf(g1y, v01x, -g1x * v01y));
            // w(a,a') = sum_c conj(phi(a^c)) h(c,a')
            const float w00  = fmaf(g0x, h00x, g0y * h00y) + fmaf(g1x, h10x, g1y * h10y);
            const float w01x = fmaf(g0x, h01x, g0y * h01y) + fmaf(g1x, h11x, g1y * h11y);
            const float w01y = fmaf(g0x, h01y, -g0y * h01x) + fmaf(g1x, h11y, -g1y * h11x);
            const float w11  = fmaf(g1x, h01x, g1y * h01y) + fmaf(g0x, h11x, g0y * h11y);
            // v_new = M .* w
            v00  =  gm * w00;
            v11  = -gm * w11;
            v01x = fmaf(gux, w01x, -guy * w01y);
            v01y = fmaf(gux, w01y,  guy * w01x);
        }
    }

    {
        const float ev = v00 + v11 + 2.f * v01x;
        if (l == NQ - 1) my_ev = ev;
    }

    if (l < NQ) out[e * NQ + l] = my_ev;
}

extern "C" void kernel_launch(void* const* d_in, const int* in_sizes, int n_in,
                              void* d_out, int out_size)
{
    const float* x = (const float*)d_in[0];   // (B, 13) float32
    const float* w = (const float*)d_in[1];   // (2, 13, 3) float32
    float* out     = (float*)d_out;           // (B, 13) float32

    const int B = in_sizes[0] / NQ;           // 512
    const int blocks = (B + 3) / 4;           // 128 CTAs x 128 threads
    qsim_tn<<<blocks, 128>>>(x, w, out, B);
}

// round 11
// speedup vs baseline: 1.3478x; 1.3478x over previous
#include <cuda_runtime.h>

#define NQ 13
#define FULL 0xffffffffu

// Transfer-matrix contraction (bond dim 4, Hermitian-reduced).
// TWO batch elements per warp (independent chains interleaved for ILP-based
// latency hiding), 4 warps per CTA -> 64 CTAs, 256 warps total.
//   - lanes 0..12:  layer-1 phi for wire l, for BOTH elements (6 sincosf)
//   - lanes 16..28: layer-2 (m,mu) for wire l-16, BOTH elements (4 sincosf)
//   - all lanes run both 13-step chains; params broadcast via shfl;
//     kappa derived in-lane from shuffled phi.
//   - ev_A[q] kept by lane q, ev_B[q] by lane 16+q -> two coalesced stores.
// Math (verified R5-R10):
//   layer-2 M = U2+ Z U2, RZ cancels: m = cos t1 cos t2,
//     mu = -sin t2 - i sin t1 cos t2  (FULL angles t = x*w)
//   layer-1 phi = first column of RZ*RY*RX (half angles)
//   CNOT chain = Gray perm -> nearest-neighbor transfer chain; identity tail
//   telescopes to boundary kappa_{q+1} = 2 Re(conj(phi0) phi1).
__global__ __launch_bounds__(128, 1)
void qsim_tn(const float* __restrict__ x,
             const float* __restrict__ wts,
             float* __restrict__ out,
             int n)
{
    const int W  = blockIdx.x * 4 + (threadIdx.x >> 5);   // warp id
    const int l  = threadIdx.x & 31;
    const int e0 = 2 * W;
    const int e1 = 2 * W + 1;
    if (e0 >= n) return;
    const bool hasB = (e1 < n);

    // ---- per-lane gate parameters, both elements ----
    float p0xA = 0.f, p0yA = 0.f, p1xA = 0.f, p1yA = 0.f;
    float p0xB = 0.f, p0yB = 0.f, p1xB = 0.f, p1yB = 0.f;
    float mA = 0.f, muxA = 0.f, muyA = 0.f;
    float mB = 0.f, muxB = 0.f, muyB = 0.f;

    if (l < NQ) {
        const float w0 = __ldg(&wts[l * 3 + 0]);
        const float w1 = __ldg(&wts[l * 3 + 1]);
        const float w2 = __ldg(&wts[l * 3 + 2]);
        const float xA = __ldg(&x[e0 * NQ + l]);
        const float xB = hasB ? __ldg(&x[e1 * NQ + l]) : 0.f;
        float s1, c1, s2, c2, sp, cp;
        // element A
        __sincosf(0.5f * xA * w0, &s1, &c1);
        __sincosf(0.5f * xA * w1, &s2, &c2);
        __sincosf(0.5f * w2,      &sp, &cp);
        {
            const float A = c2 * c1, B = s2 * s1, C = s2 * c1, D = c2 * s1;
            p0xA = fmaf(cp, A,  sp * B);
            p0yA = fmaf(cp, B, -sp * A);
            p1xA = fmaf(cp, C,  sp * D);
            p1yA = fmaf(sp, C, -cp * D);
        }
        // element B (same sp,cp: RZ weight-only)
        __sincosf(0.5f * xB * w0, &s1, &c1);
        __sincosf(0.5f * xB * w1, &s2, &c2);
        {
            const float A = c2 * c1, B = s2 * s1, C = s2 * c1, D = c2 * s1;
            p0xB = fmaf(cp, A,  sp * B);
            p0yB = fmaf(cp, B, -sp * A);
            p1xB = fmaf(cp, C,  sp * D);
            p1yB = fmaf(sp, C, -cp * D);
        }
    } else if (l >= 16 && l < 16 + NQ) {
        const int q = l - 16;
        const float w0 = __ldg(&wts[(NQ + q) * 3 + 0]);
        const float w1 = __ldg(&wts[(NQ + q) * 3 + 1]);
        const float xA = __ldg(&x[e0 * NQ + q]);
        const float xB = hasB ? __ldg(&x[e1 * NQ + q]) : 0.f;
        float sa, ca, sb, cb;
        __sincosf(xA * w0, &sa, &ca);
        __sincosf(xA * w1, &sb, &cb);
        mA = ca * cb;  muxA = -sb;  muyA = -sa * cb;
        __sincosf(xB * w0, &sa, &ca);
        __sincosf(xB * w1, &sb, &cb);
        mB = ca * cb;  muxB = -sb;  muyB = -sa * cb;
    }

    // ---- two interleaved sequential chains ----
    float a00 = 0.f, a11 = 0.f, a01x = 0.f, a01y = 0.f;   // element A
    float b00 = 0.f, b11 = 0.f, b01x = 0.f, b01y = 0.f;   // element B
    float evA = 0.f, evB = 0.f;

    #pragma unroll
    for (int q = 0; q < NQ; q++) {
        const float A0x = __shfl_sync(FULL, p0xA, q);
        const float A0y = __shfl_sync(FULL, p0yA, q);
        const float A1x = __shfl_sync(FULL, p1xA, q);
        const float A1y = __shfl_sync(FULL, p1yA, q);
        const float AM  = __shfl_sync(FULL, mA,   16 + q);
        const float AUx = __shfl_sync(FULL, muxA, 16 + q);
        const float AUy = __shfl_sync(FULL, muyA, 16 + q);
        const float B0x = __shfl_sync(FULL, p0xB, q);
        const float B0y = __shfl_sync(FULL, p0yB, q);
        const float B1x = __shfl_sync(FULL, p1xB, q);
        const float B1y = __shfl_sync(FULL, p1yB, q);
        const float BM  = __shfl_sync(FULL, mB,   16 + q);
        const float BUx = __shfl_sync(FULL, muxB, 16 + q);
        const float BUy = __shfl_sync(FULL, muyB, 16 + q);

        if (q > 0) {
            const float kA = 2.f * fmaf(A0x, A1x, A0y * A1y);
            const float kB = 2.f * fmaf(B0x, B1x, B0y * B1y);
            const float eA = a00 + a11 + kA * (2.f * a01x);
            const float eB = b00 + b11 + kB * (2.f * b01x);
            if (l == q - 1)      evA = eA;
            if (l == 16 + q - 1) evB = eB;
        }

        if (q == 0) {
            a00  =  AM * fmaf(A0x, A0x, A0y * A0y);
            a11  = -AM * fmaf(A1x, A1x, A1y * A1y);
            const float tax = fmaf(A0x, A1x,  A0y * A1y);
            const float tay = fmaf(A0x, A1y, -A0y * A1x);
            a01x = fmaf(AUx, tax, -AUy * tay);
            a01y = fmaf(AUx, tay,  AUy * tax);
            b00  =  BM * fmaf(B0x, B0x, B0y * B0y);
            b11  = -BM * fmaf(B1x, B1x, B1y * B1y);
            const float tbx = fmaf(B0x, B1x,  B0y * B1y);
            const float tby = fmaf(B0x, B1y, -B0y * B1x);
            b01x = fmaf(BUx, tbx, -BUy * tby);
            b01y = fmaf(BUx, tby,  BUy * tbx);
        } else {
            // ---- chain A ----
            {
                const float h00x = fmaf(A0x, a00, fmaf(A1x, a01x, -A1y * a01y));
                const float h00y = fmaf(A0y, a00, fmaf(A1x, a01y,  A1y * a01x));
                const float h01x = fmaf(A1x, a00, fmaf(A0x, a01x, -A0y * a01y));
                const float h01y = fmaf(A1y, a00, fmaf(A0x, a01y,  A0y * a01x));
                const float h10x = fmaf(A1x, a11, fmaf(A0x, a01x,  A0y * a01y));
                const float h10y = fmaf(A1y, a11, fmaf(A0y, a01x, -A0x * a01y));
                const float h11x = fmaf(A0x, a11, fmaf(A1x, a01x,  A1y * a01y));
                const float h11y = fmaf(A0y, a11, fmaf(A1y, a01x, -A1x * a01y));
                const float w00  = fmaf(A0x, h00x, A0y * h00y) + fmaf(A1x, h10x, A1y * h10y);
                const float w01x = fmaf(A0x, h01x, A0y * h01y) + fmaf(A1x, h11x, A1y * h11y);
                const float w01y = fmaf(A0x, h01y, -A0y * h01x) + fmaf(A1x, h11y, -A1y * h11x);
                const float w11  = fmaf(A1x, h01x, A1y * h01y) + fmaf(A0x, h11x, A0y * h11y);
                a00  =  AM * w00;
                a11  = -AM * w11;
                a01x = fmaf(AUx, w01x, -AUy * w01y);
                a01y = fmaf(AUx, w01y,  AUy * w01x);
            }
            // ---- chain B (independent; fills A's latency) ----
            {
                const float h00x = fmaf(B0x, b00, fmaf(B1x, b01x, -B1y * b01y));
                const float h00y = fmaf(B0y, b00, fmaf(B1x, b01y,  B1y * b01x));
                const float h01x = fmaf(B1x, b00, fmaf(B0x, b01x, -B0y * b01y));
                const float h01y = fmaf(B1y, b00, fmaf(B0x, b01y,  B0y * b01x));
                const float h10x = fmaf(B1x, b11, fmaf(B0x, b01x,  B0y * b01y));
                const float h10y = fmaf(B1y, b11, fmaf(B0y, b01x, -B0x * b01y));
                const float h11x = fmaf(B0x, b11, fmaf(B1x, b01x,  B1y * b01y));
                const float h11y = fmaf(B0y, b11, fmaf(B1y, b01x, -B1x * b01y));
                const float w00  = fmaf(B0x, h00x, B0y * h00y) + fmaf(B1x, h10x, B1y * h10y);
                const float w01x = fmaf(B0x, h01x, B0y * h01y) + fmaf(B1x, h11x, B1y * h11y);
                const float w01y = fmaf(B0x, h01y, -B0y * h01x) + fmaf(B1x, h11y, -B1y * h11x);
                const float w11  = fmaf(B1x, h01x, B1y * h01y) + fmaf(B0x, h11x, B0y * h11y);
                b00  =  BM * w00;
                b11  = -BM * w11;
                b01x = fmaf(BUx, w01x, -BUy * w01y);
                b01y = fmaf(BUx, w01y,  BUy * w01x);
            }
        }
    }

    {
        const float eA = a00 + a11 + 2.f * a01x;
        const float eB = b00 + b11 + 2.f * b01x;
        if (l == NQ - 1)      evA = eA;
        if (l == 16 + NQ - 1) evB = eB;
    }

    if (l < NQ) out[e0 * NQ + l] = evA;
    if (hasB && l >= 16 && l < 16 + NQ) out[e1 * NQ + (l - 16)] = evB;
}

extern "C" void kernel_launch(void* const* d_in, const int* in_sizes, int n_in,
                              void* d_out, int out_size)
{
    const float* x = (const float*)d_in[0];   // (B, 13) float32
    const float* w = (const float*)d_in[1];   // (2, 13, 3) float32
    float* out     = (float*)d_out;           // (B, 13) float32

    const int B = in_sizes[0] / NQ;           // 512
    const int warps  = (B + 1) / 2;           // 256 warps (2 elems/warp)
    const int blocks = (warps + 3) / 4;       // 64 CTAs x 128 threads
    qsim_tn<<<blocks, 128>>>(x, w, out, B);
}